// round 15
// baseline (speedup 1.0000x reference)
#include <cuda_runtime.h>
#include <cuda_bf16.h>
#include <cstdint>

#define FDIM 128
#define S_N 50000
#define T_N 50000
#define E_N 600000
#define F2 256
#define F4 512
#define SLOPE 0.1f
#define BN_EPS 1e-5f

#define PA 24          // smem pitch (48B rows: 16B-aligned, conflict-free ldmatrix)
#define TBM 64         // CTA tile M (all GEMMs, 256 threads)

#define AEL (TBM * PA)         // 1536 elems per A half-slab
#define BEL4 (F2 * PA)         // 6144 elems per B half-slab (N=256)
#define BEL2 (FDIM * PA)       // 3072 elems per B half-slab (N=128)
#define SMEM4 ((4 * AEL + 4 * BEL4) * 2)   // 61440 B (pre/node1)
#define SMEM2 ((4 * AEL + 4 * BEL2) * 2)   // 36864 B (node2)

// Persistent edge kernel smem map (bytes):
//   B_hi: 0..65536   B_lo: 65536..131072   (256 rows x 128 cols, pitch16+XOR swizzle)
//   A_hi: 131072 + s*3072 (8 slabs, pitch 24)   A_lo: 155648 + s*3072
#define EB_HI   0
#define EB_LO   65536
#define EA_HI   131072
#define EA_LO   155648
#define EDYN_P  180224

// ---------------------------------------------------------------------------
// Scratch (device globals — no runtime allocation allowed)
// ---------------------------------------------------------------------------
__device__ float  g_P[(size_t)S_N * F2];
__device__ float  g_aggH[(size_t)T_N * F2];
__device__ float  g_h3[(size_t)T_N * F4];
__device__ float  g_Wmid[(size_t)F2 * F4];
__device__ float  g_bvec[F4];
__device__ float  g_c2[F4];
__device__ int    g_cnt[T_N];
__device__ double g_sum[FDIM];
__device__ double g_sumsq[FDIM];
// Pre-split bf16 weights, transposed to [n][k]
__device__ __align__(16) __nv_bfloat16 g_Bpre_hi[(size_t)F2 * FDIM];
__device__ __align__(16) __nv_bfloat16 g_Bpre_lo[(size_t)F2 * FDIM];
__device__ __align__(16) __nv_bfloat16 g_Bedge_hi[(size_t)F2 * FDIM];
__device__ __align__(16) __nv_bfloat16 g_Bedge_lo[(size_t)F2 * FDIM];
__device__ __align__(16) __nv_bfloat16 g_Bn1_hi[(size_t)F4 * 384];
__device__ __align__(16) __nv_bfloat16 g_Bn1_lo[(size_t)F4 * 384];
__device__ __align__(16) __nv_bfloat16 g_Bn2_hi[(size_t)FDIM * F4];
__device__ __align__(16) __nv_bfloat16 g_Bn2_lo[(size_t)FDIM * F4];

// ---------------------------------------------------------------------------
// Helpers
// ---------------------------------------------------------------------------
__device__ __forceinline__ unsigned smem_u32(const void* p) {
    unsigned a;
    asm("{ .reg .u64 t; cvta.to.shared.u64 t, %1; cvt.u32.u64 %0, t; }"
        : "=r"(a) : "l"(p));
    return a;
}
__device__ __forceinline__ void ldsm4(unsigned& r0, unsigned& r1, unsigned& r2,
                                      unsigned& r3, unsigned addr) {
    asm volatile("ldmatrix.sync.aligned.m8n8.x4.shared.b16 {%0,%1,%2,%3}, [%4];"
                 : "=r"(r0), "=r"(r1), "=r"(r2), "=r"(r3) : "r"(addr));
}
__device__ __forceinline__ void mma16816(float* c, const unsigned* a, const unsigned* b) {
    asm volatile(
        "mma.sync.aligned.m16n8k16.row.col.f32.bf16.bf16.f32 "
        "{%0,%1,%2,%3}, {%4,%5,%6,%7}, {%8,%9}, {%0,%1,%2,%3};"
        : "+f"(c[0]), "+f"(c[1]), "+f"(c[2]), "+f"(c[3])
        : "r"(a[0]), "r"(a[1]), "r"(a[2]), "r"(a[3]), "r"(b[0]), "r"(b[1]));
}
__device__ __forceinline__ void red_add_v2(float* p, float a, float b) {
    asm volatile("red.global.add.v2.f32 [%0], {%1, %2};"
                 :: "l"(p), "f"(a), "f"(b) : "memory");
}
__device__ __forceinline__ void split_store(__nv_bfloat16* ph, __nv_bfloat16* pl, float2 v) {
    __nv_bfloat16 hx = __float2bfloat16_rn(v.x);
    __nv_bfloat16 hy = __float2bfloat16_rn(v.y);
    __nv_bfloat16 lx = __float2bfloat16_rn(v.x - __bfloat162float(hx));
    __nv_bfloat16 ly = __float2bfloat16_rn(v.y - __bfloat162float(hy));
    __nv_bfloat162 h; h.x = hx; h.y = hy;
    __nv_bfloat162 l; l.x = lx; l.y = ly;
    *reinterpret_cast<__nv_bfloat162*>(ph) = h;
    *reinterpret_cast<__nv_bfloat162*>(pl) = l;
}

// One K=16 slab of warp-level split-bf16 MMAs.  acc[mi*2NT + ni][4]
// BSTR = byte stride between consecutive 16-row B blocks (p2 steps).
template<int NT, int BSTR>
__device__ __forceinline__ void mma_chunk_t(unsigned aH, unsigned aL,
                                            unsigned bHa, unsigned bLa,
                                            float (*acc)[4]) {
    unsigned ah[2][4], al[2][4];
    ldsm4(ah[0][0], ah[0][1], ah[0][2], ah[0][3], aH);
    ldsm4(ah[1][0], ah[1][1], ah[1][2], ah[1][3], aH + 16 * PA * 2);
    ldsm4(al[0][0], al[0][1], al[0][2], al[0][3], aL);
    ldsm4(al[1][0], al[1][1], al[1][2], al[1][3], aL + 16 * PA * 2);
    #pragma unroll
    for (int p2 = 0; p2 < NT; p2++) {
        unsigned bh[4], bl[4];
        ldsm4(bh[0], bh[1], bh[2], bh[3], bHa + p2 * BSTR);
        ldsm4(bl[0], bl[1], bl[2], bl[3], bLa + p2 * BSTR);
        #pragma unroll
        for (int mi = 0; mi < 2; mi++)
            #pragma unroll
            for (int t = 0; t < 2; t++) {
                float* c = acc[mi * (2 * NT) + 2 * p2 + t];
                mma16816(c, ah[mi], &bh[2 * t]);
                mma16816(c, ah[mi], &bl[2 * t]);
                mma16816(c, al[mi], &bh[2 * t]);
            }
    }
}

// Warp layout (8 warps): (warp>>2) m-tiles of 32, (warp&3) n-blocks of NT*16
#define MAKE_LANE(NTv)                                                           \
    int lane = threadIdx.x & 31;                                                 \
    int warp = threadIdx.x >> 5;                                                 \
    int wm0 = (warp >> 2) * 32;                                                  \
    int wn0 = (warp & 3) * ((NTv) * 16);                                         \
    unsigned aOff =                                                              \
        ((wm0 + ((lane >> 3) & 1) * 8 + (lane & 7)) * PA + (lane >> 4) * 8) * 2; \
    unsigned bOff =                                                              \
        ((wn0 + (lane >> 4) * 8 + (lane & 7)) * PA + ((lane >> 3) & 1) * 8) * 2;

#define OFF_AH(s)        ((s) * AEL * 2)
#define OFF_AL(s)        ((2 * AEL + (s) * AEL) * 2)
#define OFF_BH(s, BELv)  ((4 * AEL + (s) * (BELv)) * 2)
#define OFF_BL(s, BELv)  ((4 * AEL + 2 * (BELv) + (s) * (BELv)) * 2)

#define LOAD_B_SLAB(pBh, pBl, Bhi, Blo, K, TBN_, k0)                            \
    for (int p = threadIdx.x; p < (TBN_) * 2; p += 256) {                       \
        int n = p >> 1, j = p & 1;                                              \
        *reinterpret_cast<uint4*>(&(pBh)[n * PA + 8 * j]) =                     \
            *reinterpret_cast<const uint4*>(&(Bhi)[(size_t)n * (K) + (k0) + 8 * j]); \
        *reinterpret_cast<uint4*>(&(pBl)[n * PA + 8 * j]) =                     \
            *reinterpret_cast<const uint4*>(&(Blo)[(size_t)n * (K) + (k0) + 8 * j]); \
    }

extern __shared__ __align__(16) __nv_bfloat16 dsm[];

// ---------------------------------------------------------------------------
__global__ void zero_kernel() {
    int idx = blockIdx.x * blockDim.x + threadIdx.x;
    int stride = gridDim.x * blockDim.x;
    float4* a4 = reinterpret_cast<float4*>(g_aggH);
    const float4 z = make_float4(0.f, 0.f, 0.f, 0.f);
    for (size_t i = idx; i < (size_t)T_N * F2 / 4; i += stride) a4[i] = z;
    for (int i = idx; i < T_N; i += stride) g_cnt[i] = 0;
    if (idx < FDIM) { g_sum[idx] = 0.0; g_sumsq[idx] = 0.0; }
}

__device__ __forceinline__ void split1(__nv_bfloat16* ph, __nv_bfloat16* pl, float v) {
    __nv_bfloat16 h = __float2bfloat16_rn(v);
    *ph = h;
    *pl = __float2bfloat16_rn(v - __bfloat162float(h));
}

__global__ void convert_B1(const float* __restrict__ W1a) {
    int idx = blockIdx.x * blockDim.x + threadIdx.x;
    if (idx >= 2 * F2 * FDIM) return;
    int half = idx >= F2 * FDIM;
    int l = idx - half * (F2 * FDIM);
    int n = l >> 7, k = l & 127;
    if (!half)
        split1(&g_Bpre_hi[l], &g_Bpre_lo[l], W1a[(size_t)k * F2 + n]);
    else
        split1(&g_Bedge_hi[l], &g_Bedge_lo[l], W1a[(size_t)(FDIM + k) * F2 + n]);
}

__global__ void __launch_bounds__(512) compute_Wmid(
    const float* __restrict__ W1b, const float* __restrict__ W2a)
{
    __shared__ float sRow[F2];
    int k = blockIdx.x;
    int j = threadIdx.x;
    if (j < F2) sRow[j] = W1b[(size_t)k * F2 + j];
    __syncthreads();
    float acc = 0.f;
    #pragma unroll 4
    for (int m = 0; m < F2; m++)
        acc = fmaf(sRow[m], W2a[(size_t)(128 + m) * F4 + j], acc);
    g_Wmid[(size_t)k * F4 + j] = acc;
}

__global__ void __launch_bounds__(512) compute_vecs(
    const float* __restrict__ b1b, const float* __restrict__ u,
    const float* __restrict__ W2a, const float* __restrict__ b2a)
{
    int j = threadIdx.x;
    float bv = 0.f;
    for (int m = 0; m < F2; m++)
        bv = fmaf(b1b[m], W2a[(size_t)(128 + m) * F4 + j], bv);
    g_bvec[j] = bv;
    float cv = b2a[j];
    for (int k = 0; k < FDIM; k++)
        cv = fmaf(u[k], W2a[(size_t)(384 + k) * F4 + j], cv);
    g_c2[j] = cv;
}

__global__ void convert_Bn1(const float* __restrict__ W2a) {
    int idx = blockIdx.x * blockDim.x + threadIdx.x;
    if (idx >= F4 * 384) return;
    int n = idx / 384, k = idx % 384;
    float v = (k < FDIM) ? W2a[(size_t)k * F4 + n] : g_Wmid[(size_t)(k - FDIM) * F4 + n];
    split1(&g_Bn1_hi[idx], &g_Bn1_lo[idx], v);
}
__global__ void convert_Bn2(const float* __restrict__ W2b) {
    int idx = blockIdx.x * blockDim.x + threadIdx.x;
    if (idx >= FDIM * F4) return;
    int n = idx >> 9, k = idx & 511;
    split1(&g_Bn2_hi[idx], &g_Bn2_lo[idx], W2b[(size_t)k * FDIM + n]);
}

// ---------------------------------------------------------------------------
// GEMM pre: x_s[S,128] @ Bpre^T -> g_P (+ b1a).  N=256, K=128, 2 slabs/iter.
// ---------------------------------------------------------------------------
__global__ void __launch_bounds__(256, 2) gemm_pre(
    const float* __restrict__ x_s, const float* __restrict__ b1a)
{
    int m0 = blockIdx.x * TBM;
    MAKE_LANE(4);
    unsigned base = smem_u32(dsm);
    float acc[16][4] = {};

    for (int kt = 0; kt < FDIM; kt += 32) {
        #pragma unroll
        for (int s = 0; s < 2; s++) {
            int k0 = kt + 16 * s;
            __nv_bfloat16* pAh = dsm + s * AEL;
            __nv_bfloat16* pAl = dsm + 2 * AEL + s * AEL;
            #pragma unroll
            for (int it = 0; it < 2; it++) {
                int p = threadIdx.x + it * 256;
                int row = p >> 3, cp = p & 7;
                int gm = m0 + row;
                float2 v = make_float2(0.f, 0.f);
                if (gm < S_N)
                    v = *reinterpret_cast<const float2*>(
                            x_s + (size_t)gm * FDIM + k0 + 2 * cp);
                split_store(&pAh[row * PA + 2 * cp], &pAl[row * PA + 2 * cp], v);
            }
            __nv_bfloat16* pBh = dsm + 4 * AEL + s * BEL4;
            __nv_bfloat16* pBl = dsm + 4 * AEL + 2 * BEL4 + s * BEL4;
            LOAD_B_SLAB(pBh, pBl, g_Bpre_hi, g_Bpre_lo, FDIM, F2, k0);
        }
        __syncthreads();
        #pragma unroll
        for (int s = 0; s < 2; s++)
            mma_chunk_t<4, 16 * PA * 2>(
                base + OFF_AH(s) + aOff, base + OFF_AL(s) + aOff,
                base + OFF_BH(s, BEL4) + bOff, base + OFF_BL(s, BEL4) + bOff, acc);
        __syncthreads();
    }

    #pragma unroll
    for (int mi = 0; mi < 2; mi++)
        #pragma unroll
        for (int h = 0; h < 2; h++) {
            int gm = m0 + wm0 + mi * 16 + (lane >> 2) + h * 8;
            if (gm >= S_N) continue;
            #pragma unroll
            for (int ni = 0; ni < 8; ni++) {
                int col = wn0 + ni * 8 + 2 * (lane & 3);
                float2 bb = *reinterpret_cast<const float2*>(b1a + col);
                float2 o;
                o.x = acc[mi * 8 + ni][h * 2 + 0] + bb.x;
                o.y = acc[mi * 8 + ni][h * 2 + 1] + bb.y;
                *reinterpret_cast<float2*>(&g_P[(size_t)gm * F2 + col]) = o;
            }
        }
}

// ---------------------------------------------------------------------------
// Persistent GEMM edge: B resident in smem (loaded once), loop over M tiles.
// B layout: pitch 16 elems/row-chunk with XOR swizzle:
//   byte(n, s, j) = n*256 + s*32 + ((j ^ ((n>>2)&1)) << 4)
// ---------------------------------------------------------------------------
__global__ void __launch_bounds__(256, 1) gemm_edge(
    const float* __restrict__ edge_attr, const int* __restrict__ eidx)
{
    __shared__ int sSrc[TBM], sTgt[TBM];
    char* smc = reinterpret_cast<char*>(dsm);
    unsigned base = smem_u32(dsm);

    // Prologue: load B (hi/lo) once into swizzled layout.
    for (int p = threadIdx.x; p < 4096; p += 256) {
        int n = p >> 4, s = (p >> 1) & 7, j = p & 1;
        unsigned off = n * 256 + s * 32 + ((j ^ ((n >> 2) & 1)) << 4);
        *reinterpret_cast<uint4*>(smc + EB_HI + off) =
            *reinterpret_cast<const uint4*>(&g_Bedge_hi[(size_t)n * FDIM + s * 16 + j * 8]);
        *reinterpret_cast<uint4*>(smc + EB_LO + off) =
            *reinterpret_cast<const uint4*>(&g_Bedge_lo[(size_t)n * FDIM + s * 16 + j * 8]);
    }

    int lane = threadIdx.x & 31;
    int warp = threadIdx.x >> 5;
    int wm0 = (warp >> 2) * 32;
    int wn0 = (warp & 3) * 64;
    unsigned aOff =
        ((wm0 + ((lane >> 3) & 1) * 8 + (lane & 7)) * PA + (lane >> 4) * 8) * 2;
    {
        // B per-lane address: row = wn0 + (lane>>4)*8 + (lane&7); colhalf = (lane>>3)&1
    }
    int brow = wn0 + ((lane >> 4) << 3) + (lane & 7);
    int bcolh = (lane >> 3) & 1;
    unsigned bOffP = (unsigned)(brow * 256 + ((bcolh ^ ((brow >> 2) & 1)) << 4));

    __syncthreads();

    const int NTILES = E_N / TBM;   // 9375
    for (int tile = blockIdx.x; tile < NTILES; tile += gridDim.x) {
        int m0 = tile * TBM;

        if (threadIdx.x < TBM) {
            int m = m0 + threadIdx.x;
            int sv = eidx[m];
            int tv = eidx[E_N + m];
            atomicAdd(&g_cnt[tv], 1);
            sSrc[threadIdx.x] = sv;
            sTgt[threadIdx.x] = tv;
        }

        // Load + convert A tile (64 rows x 128 cols) into 8 slabs.
        #pragma unroll
        for (int it = 0; it < 16; it++) {
            int p = threadIdx.x + it * 256;
            int row = p >> 6, cp = p & 63;        // cp = float2 index in row
            float2 v = *reinterpret_cast<const float2*>(
                    edge_attr + (size_t)(m0 + row) * FDIM + 2 * cp);
            int s = cp >> 3;
            int ic = (cp & 7) * 2;
            __nv_bfloat16* pAh = reinterpret_cast<__nv_bfloat16*>(smc + EA_HI + s * 3072);
            __nv_bfloat16* pAl = reinterpret_cast<__nv_bfloat16*>(smc + EA_LO + s * 3072);
            split_store(&pAh[row * PA + ic], &pAl[row * PA + ic], v);
        }
        __syncthreads();

        float acc[16][4] = {};
        #pragma unroll
        for (int s = 0; s < 8; s++)
            mma_chunk_t<4, 4096>(
                base + EA_HI + s * 3072 + aOff, base + EA_LO + s * 3072 + aOff,
                base + EB_HI + bOffP + s * 32, base + EB_LO + bOffP + s * 32, acc);

        #pragma unroll
        for (int mi = 0; mi < 2; mi++)
            #pragma unroll
            for (int h = 0; h < 2; h++) {
                int r = wm0 + mi * 16 + (lane >> 2) + h * 8;
                int s = sSrc[r], t = sTgt[r];
                #pragma unroll
                for (int ni = 0; ni < 8; ni++) {
                    int col = wn0 + ni * 8 + 2 * (lane & 3);
                    float2 pv = *reinterpret_cast<const float2*>(&g_P[(size_t)s * F2 + col]);
                    float v0 = acc[mi * 8 + ni][h * 2 + 0] + pv.x;
                    float v1 = acc[mi * 8 + ni][h * 2 + 1] + pv.y;
                    v0 = v0 >= 0.f ? v0 : SLOPE * v0;
                    v1 = v1 >= 0.f ? v1 : SLOPE * v1;
                    red_add_v2(&g_aggH[(size_t)t * F2 + col], v0, v1);
                }
            }
        __syncthreads();
    }
}

// ---------------------------------------------------------------------------
// GEMM node1: [x_t | aggH][T,384] @ Bn1^T; epi leaky(+c2+cnt*bvec) -> g_h3
// ---------------------------------------------------------------------------
__global__ void __launch_bounds__(256, 2) gemm_node1(const float* __restrict__ x_t)
{
    int m0 = blockIdx.y * TBM;
    int n0 = blockIdx.x * F2;
    MAKE_LANE(4);
    unsigned base = smem_u32(dsm);
    float acc[16][4] = {};

    for (int kt = 0; kt < 384; kt += 32) {
        #pragma unroll
        for (int s = 0; s < 2; s++) {
            int k0 = kt + 16 * s;
            __nv_bfloat16* pAh = dsm + s * AEL;
            __nv_bfloat16* pAl = dsm + 2 * AEL + s * AEL;
            #pragma unroll
            for (int it = 0; it < 2; it++) {
                int p = threadIdx.x + it * 256;
                int row = p >> 3, cp = p & 7;
                int gm = m0 + row;
                int gk = k0 + 2 * cp;
                float2 v = make_float2(0.f, 0.f);
                if (gm < T_N) {
                    if (gk < FDIM)
                        v = *reinterpret_cast<const float2*>(x_t + (size_t)gm * FDIM + gk);
                    else
                        v = *reinterpret_cast<const float2*>(
                                &g_aggH[(size_t)gm * F2 + gk - FDIM]);
                }
                split_store(&pAh[row * PA + 2 * cp], &pAl[row * PA + 2 * cp], v);
            }
            const __nv_bfloat16* Bh = g_Bn1_hi + (size_t)n0 * 384;
            const __nv_bfloat16* Bl = g_Bn1_lo + (size_t)n0 * 384;
            __nv_bfloat16* pBh = dsm + 4 * AEL + s * BEL4;
            __nv_bfloat16* pBl = dsm + 4 * AEL + 2 * BEL4 + s * BEL4;
            LOAD_B_SLAB(pBh, pBl, Bh, Bl, 384, F2, k0);
        }
        __syncthreads();
        #pragma unroll
        for (int s = 0; s < 2; s++)
            mma_chunk_t<4, 16 * PA * 2>(
                base + OFF_AH(s) + aOff, base + OFF_AL(s) + aOff,
                base + OFF_BH(s, BEL4) + bOff, base + OFF_BL(s, BEL4) + bOff, acc);
        __syncthreads();
    }

    #pragma unroll
    for (int mi = 0; mi < 2; mi++)
        #pragma unroll
        for (int h = 0; h < 2; h++) {
            int gm = m0 + wm0 + mi * 16 + (lane >> 2) + h * 8;
            if (gm >= T_N) continue;
            float c = (float)g_cnt[gm];
            #pragma unroll
            for (int ni = 0; ni < 8; ni++) {
                int col = n0 + wn0 + ni * 8 + 2 * (lane & 3);
                float2 c2v = *reinterpret_cast<const float2*>(&g_c2[col]);
                float2 bvv = *reinterpret_cast<const float2*>(&g_bvec[col]);
                float v0 = acc[mi * 8 + ni][h * 2 + 0] + c2v.x + c * bvv.x;
                float v1 = acc[mi * 8 + ni][h * 2 + 1] + c2v.y + c * bvv.y;
                v0 = v0 >= 0.f ? v0 : SLOPE * v0;
                v1 = v1 >= 0.f ? v1 : SLOPE * v1;
                float2 o; o.x = v0; o.y = v1;
                *reinterpret_cast<float2*>(&g_h3[(size_t)gm * F4 + col]) = o;
            }
        }
}

// ---------------------------------------------------------------------------
// GEMM node2: g_h3[T,512] @ Bn2^T (+b2b) -> out.  N=128 (NT=2), K=512.
// ---------------------------------------------------------------------------
__global__ void __launch_bounds__(256, 2) gemm_node2(
    const float* __restrict__ b2b, float* __restrict__ out)
{
    int m0 = blockIdx.x * TBM;
    MAKE_LANE(2);
    unsigned base = smem_u32(dsm);
    float acc[8][4] = {};

    for (int kt = 0; kt < F4; kt += 32) {
        #pragma unroll
        for (int s = 0; s < 2; s++) {
            int k0 = kt + 16 * s;
            __nv_bfloat16* pAh = dsm + s * AEL;
            __nv_bfloat16* pAl = dsm + 2 * AEL + s * AEL;
            #pragma unroll
            for (int it = 0; it < 2; it++) {
                int p = threadIdx.x + it * 256;
                int row = p >> 3, cp = p & 7;
                int gm = m0 + row;
                float2 v = make_float2(0.f, 0.f);
                if (gm < T_N)
                    v = *reinterpret_cast<const float2*>(
                            &g_h3[(size_t)gm * F4 + k0 + 2 * cp]);
                split_store(&pAh[row * PA + 2 * cp], &pAl[row * PA + 2 * cp], v);
            }
            __nv_bfloat16* pBh = dsm + 4 * AEL + s * BEL2;
            __nv_bfloat16* pBl = dsm + 4 * AEL + 2 * BEL2 + s * BEL2;
            LOAD_B_SLAB(pBh, pBl, g_Bn2_hi, g_Bn2_lo, F4, FDIM, k0);
        }
        __syncthreads();
        #pragma unroll
        for (int s = 0; s < 2; s++)
            mma_chunk_t<2, 16 * PA * 2>(
                base + OFF_AH(s) + aOff, base + OFF_AL(s) + aOff,
                base + OFF_BH(s, BEL2) + bOff, base + OFF_BL(s, BEL2) + bOff, acc);
        __syncthreads();
    }

    #pragma unroll
    for (int mi = 0; mi < 2; mi++)
        #pragma unroll
        for (int h = 0; h < 2; h++) {
            int gm = m0 + wm0 + mi * 16 + (lane >> 2) + h * 8;
            if (gm >= T_N) continue;
            #pragma unroll
            for (int ni = 0; ni < 4; ni++) {
                int col = wn0 + ni * 8 + 2 * (lane & 3);
                float2 bb = *reinterpret_cast<const float2*>(b2b + col);
                float2 o;
                o.x = acc[mi * 4 + ni][h * 2 + 0] + bb.x;
                o.y = acc[mi * 4 + ni][h * 2 + 1] + bb.y;
                *reinterpret_cast<float2*>(&out[(size_t)gm * FDIM + col]) = o;
            }
        }
}

// ---------------------------------------------------------------------------
// BatchNorm
// ---------------------------------------------------------------------------
__global__ void bn_stats(const float* __restrict__ y) {
    int c = threadIdx.x & (FDIM - 1);
    int half = threadIdx.x >> 7;
    double s = 0.0, sq = 0.0;
    for (int m = blockIdx.x * 2 + half; m < T_N; m += gridDim.x * 2) {
        float v = y[(size_t)m * FDIM + c];
        s += v;
        sq += (double)v * (double)v;
    }
    atomicAdd(&g_sum[c], s);
    atomicAdd(&g_sumsq[c], sq);
}

__global__ void bn_norm(float* __restrict__ y,
                        const float* __restrict__ gamma,
                        const float* __restrict__ beta) {
    size_t idx = (size_t)blockIdx.x * blockDim.x + threadIdx.x;
    if (idx >= (size_t)T_N * FDIM) return;
    int c = (int)(idx & (FDIM - 1));
    double mean = g_sum[c] / (double)T_N;
    double var = g_sumsq[c] / (double)T_N - mean * mean;
    float scale = rsqrtf((float)var + BN_EPS) * gamma[c];
    y[idx] = (float)((double)y[idx] - mean) * scale + beta[c];
}

extern "C" void kernel_launch(void* const* d_in, const int* in_sizes, int n_in,
                              void* d_out, int out_size) {
    const float* x_s       = (const float*)d_in[0];
    const float* x_t       = (const float*)d_in[1];
    const float* edge_attr = (const float*)d_in[2];
    const float* u         = (const float*)d_in[3];
    const int*   eidx      = (const int*)d_in[4];
    const float* W1a       = (const float*)d_in[5];
    const float* b1a       = (const float*)d_in[6];
    const float* W1b       = (const float*)d_in[7];
    const float* b1b       = (const float*)d_in[8];
    const float* W2a       = (const float*)d_in[9];
    const float* b2a       = (const float*)d_in[10];
    const float* W2b       = (const float*)d_in[11];
    const float* b2b       = (const float*)d_in[12];
    const float* gamma     = (const float*)d_in[13];
    const float* beta      = (const float*)d_in[14];
    float* out = (float*)d_out;

    static int smem_set = 0;
    if (!smem_set) {
        cudaFuncSetAttribute(gemm_pre,   cudaFuncAttributeMaxDynamicSharedMemorySize, SMEM4);
        cudaFuncSetAttribute(gemm_edge,  cudaFuncAttributeMaxDynamicSharedMemorySize, EDYN_P);
        cudaFuncSetAttribute(gemm_node1, cudaFuncAttributeMaxDynamicSharedMemorySize, SMEM4);
        cudaFuncSetAttribute(gemm_node2, cudaFuncAttributeMaxDynamicSharedMemorySize, SMEM2);
        smem_set = 1;
    }

    // Launch order chosen so the ncu capture slot (4th launch) is gemm_edge.
    convert_B1<<<(2 * F2 * FDIM + 255) / 256, 256>>>(W1a);           // 1
    zero_kernel<<<1024, 256>>>();                                    // 2

    int mblk = (S_N + TBM - 1) / TBM;               // 782
    gemm_pre<<<mblk, 256, SMEM4>>>(x_s, b1a);                        // 3

    gemm_edge<<<148, 256, EDYN_P>>>(edge_attr, eidx);                // 4 (persistent)

    compute_Wmid<<<F2, 512>>>(W1b, W2a);                             // 5
    compute_vecs<<<1, 512>>>(b1b, u, W2a, b2a);                      // 6
    convert_Bn1<<<(F4 * 384 + 255) / 256, 256>>>(W2a);               // 7
    convert_Bn2<<<(FDIM * F4 + 255) / 256, 256>>>(W2b);              // 8

    dim3 gN1(2, mblk);
    gemm_node1<<<gN1, 256, SMEM4>>>(x_t);                            // 9
    gemm_node2<<<mblk, 256, SMEM2>>>(b2b, out);                      // 10

    bn_stats<<<512, 256>>>(out);                                     // 11
    bn_norm<<<(T_N * FDIM + 255) / 256, 256>>>(out, gamma, beta);    // 12
}

// round 17
// speedup vs baseline: 1.2120x; 1.2120x over previous
#include <cuda_runtime.h>
#include <cuda_bf16.h>
#include <cstdint>

#define FDIM 128
#define S_N 50000
#define T_N 50000
#define E_N 600000
#define F2 256
#define F4 512
#define SLOPE 0.1f
#define BN_EPS 1e-5f

#define PA 24          // smem pitch (48B rows: 16B-aligned, conflict-free ldmatrix)
#define TBM 64         // CTA tile M (non-edge kernels)
#define TBME 128       // CTA tile M (edge kernel, 512 threads)

#define AEL (TBM * PA)         // 1536 elems per A half-slab
#define BEL4 (F2 * PA)         // 6144 elems per B half-slab (N=256)
#define BEL2 (FDIM * PA)       // 3072 elems per B half-slab (N=128)
#define SMEM4 ((4 * AEL + 4 * BEL4) * 2)   // 61440 B (pre/node1)
#define SMEM2 ((4 * AEL + 4 * BEL2) * 2)   // 36864 B (node2)

// Edge kernel (R11 shape): TBM=128, 512 thr, 2-stage double buffer
#define EAE (TBME * PA)            // 3072 elems (one of Ah/Al)
#define EBE (F2 * PA)              // 6144 elems (one of Bh/Bl)
#define ESTAGE (2 * EAE + 2 * EBE) // 18432 elems = 36864 B
#define EDYN (2 * ESTAGE * 2)      // 73728 B

// ---------------------------------------------------------------------------
// Scratch (device globals — no runtime allocation allowed)
// ---------------------------------------------------------------------------
__device__ float  g_P[(size_t)S_N * F2];
__device__ float  g_aggH[(size_t)T_N * F2];
__device__ float  g_h3[(size_t)T_N * F4];
__device__ float  g_Wmid[(size_t)F2 * F4];
__device__ float  g_bvec[F4];
__device__ float  g_c2[F4];
__device__ int    g_cnt[T_N];
__device__ double g_sum[FDIM];
__device__ double g_sumsq[FDIM];
// Pre-split bf16 weights, transposed to [n][k]
__device__ __align__(16) __nv_bfloat16 g_Bpre_hi[(size_t)F2 * FDIM];
__device__ __align__(16) __nv_bfloat16 g_Bpre_lo[(size_t)F2 * FDIM];
__device__ __align__(16) __nv_bfloat16 g_Bedge_hi[(size_t)F2 * FDIM];
__device__ __align__(16) __nv_bfloat16 g_Bedge_lo[(size_t)F2 * FDIM];
__device__ __align__(16) __nv_bfloat16 g_Bn1_hi[(size_t)F4 * 384];
__device__ __align__(16) __nv_bfloat16 g_Bn1_lo[(size_t)F4 * 384];
__device__ __align__(16) __nv_bfloat16 g_Bn2_hi[(size_t)FDIM * F4];
__device__ __align__(16) __nv_bfloat16 g_Bn2_lo[(size_t)FDIM * F4];

// ---------------------------------------------------------------------------
// Helpers
// ---------------------------------------------------------------------------
__device__ __forceinline__ unsigned smem_u32(const void* p) {
    unsigned a;
    asm("{ .reg .u64 t; cvta.to.shared.u64 t, %1; cvt.u32.u64 %0, t; }"
        : "=r"(a) : "l"(p));
    return a;
}
__device__ __forceinline__ void ldsm4(unsigned& r0, unsigned& r1, unsigned& r2,
                                      unsigned& r3, unsigned addr) {
    asm volatile("ldmatrix.sync.aligned.m8n8.x4.shared.b16 {%0,%1,%2,%3}, [%4];"
                 : "=r"(r0), "=r"(r1), "=r"(r2), "=r"(r3) : "r"(addr));
}
__device__ __forceinline__ void mma16816(float* c, const unsigned* a, const unsigned* b) {
    asm volatile(
        "mma.sync.aligned.m16n8k16.row.col.f32.bf16.bf16.f32 "
        "{%0,%1,%2,%3}, {%4,%5,%6,%7}, {%8,%9}, {%0,%1,%2,%3};"
        : "+f"(c[0]), "+f"(c[1]), "+f"(c[2]), "+f"(c[3])
        : "r"(a[0]), "r"(a[1]), "r"(a[2]), "r"(a[3]), "r"(b[0]), "r"(b[1]));
}
__device__ __forceinline__ void red_add_v2(float* p, float a, float b) {
    asm volatile("red.global.add.v2.f32 [%0], {%1, %2};"
                 :: "l"(p), "f"(a), "f"(b) : "memory");
}
__device__ __forceinline__ void split_store(__nv_bfloat16* ph, __nv_bfloat16* pl, float2 v) {
    __nv_bfloat16 hx = __float2bfloat16_rn(v.x);
    __nv_bfloat16 hy = __float2bfloat16_rn(v.y);
    __nv_bfloat16 lx = __float2bfloat16_rn(v.x - __bfloat162float(hx));
    __nv_bfloat16 ly = __float2bfloat16_rn(v.y - __bfloat162float(hy));
    __nv_bfloat162 h; h.x = hx; h.y = hy;
    __nv_bfloat162 l; l.x = lx; l.y = ly;
    *reinterpret_cast<__nv_bfloat162*>(ph) = h;
    *reinterpret_cast<__nv_bfloat162*>(pl) = l;
}

// One K=16 slab of warp-level split-bf16 MMAs.  acc[mi*2NT + ni][4]
template<int NT>
__device__ __forceinline__ void mma_chunk_t(unsigned aH, unsigned aL,
                                            unsigned bHa, unsigned bLa,
                                            float (*acc)[4]) {
    unsigned ah[2][4], al[2][4];
    ldsm4(ah[0][0], ah[0][1], ah[0][2], ah[0][3], aH);
    ldsm4(ah[1][0], ah[1][1], ah[1][2], ah[1][3], aH + 16 * PA * 2);
    ldsm4(al[0][0], al[0][1], al[0][2], al[0][3], aL);
    ldsm4(al[1][0], al[1][1], al[1][2], al[1][3], aL + 16 * PA * 2);
    #pragma unroll
    for (int p2 = 0; p2 < NT; p2++) {
        unsigned bh[4], bl[4];
        ldsm4(bh[0], bh[1], bh[2], bh[3], bHa + p2 * (16 * PA * 2));
        ldsm4(bl[0], bl[1], bl[2], bl[3], bLa + p2 * (16 * PA * 2));
        #pragma unroll
        for (int mi = 0; mi < 2; mi++)
            #pragma unroll
            for (int t = 0; t < 2; t++) {
                float* c = acc[mi * (2 * NT) + 2 * p2 + t];
                mma16816(c, ah[mi], &bh[2 * t]);
                mma16816(c, ah[mi], &bl[2 * t]);
                mma16816(c, al[mi], &bh[2 * t]);
            }
    }
}

// Warp layout: warps (warp>>2) m-tiles of 32, (warp&3) n-blocks of NT*16
#define MAKE_LANE(NTv)                                                           \
    int lane = threadIdx.x & 31;                                                 \
    int warp = threadIdx.x >> 5;                                                 \
    int wm0 = (warp >> 2) * 32;                                                  \
    int wn0 = (warp & 3) * ((NTv) * 16);                                         \
    unsigned aOff =                                                              \
        ((wm0 + ((lane >> 3) & 1) * 8 + (lane & 7)) * PA + (lane >> 4) * 8) * 2; \
    unsigned bOff =                                                              \
        ((wn0 + (lane >> 4) * 8 + (lane & 7)) * PA + ((lane >> 3) & 1) * 8) * 2;

#define OFF_AH(s)        ((s) * AEL * 2)
#define OFF_AL(s)        ((2 * AEL + (s) * AEL) * 2)
#define OFF_BH(s, BELv)  ((4 * AEL + (s) * (BELv)) * 2)
#define OFF_BL(s, BELv)  ((4 * AEL + 2 * (BELv) + (s) * (BELv)) * 2)

#define LOAD_B_SLAB(pBh, pBl, Bhi, Blo, K, TBN_, k0)                            \
    for (int p = threadIdx.x; p < (TBN_) * 2; p += 256) {                       \
        int n = p >> 1, j = p & 1;                                              \
        *reinterpret_cast<uint4*>(&(pBh)[n * PA + 8 * j]) =                     \
            *reinterpret_cast<const uint4*>(&(Bhi)[(size_t)n * (K) + (k0) + 8 * j]); \
        *reinterpret_cast<uint4*>(&(pBl)[n * PA + 8 * j]) =                     \
            *reinterpret_cast<const uint4*>(&(Blo)[(size_t)n * (K) + (k0) + 8 * j]); \
    }

extern __shared__ __align__(16) __nv_bfloat16 dsm[];

// ---------------------------------------------------------------------------
__global__ void zero_kernel() {
    int idx = blockIdx.x * blockDim.x + threadIdx.x;
    int stride = gridDim.x * blockDim.x;
    float4* a4 = reinterpret_cast<float4*>(g_aggH);
    const float4 z = make_float4(0.f, 0.f, 0.f, 0.f);
    for (size_t i = idx; i < (size_t)T_N * F2 / 4; i += stride) a4[i] = z;
    for (int i = idx; i < T_N; i += stride) g_cnt[i] = 0;
    if (idx < FDIM) { g_sum[idx] = 0.0; g_sumsq[idx] = 0.0; }
}

__device__ __forceinline__ void split1(__nv_bfloat16* ph, __nv_bfloat16* pl, float v) {
    __nv_bfloat16 h = __float2bfloat16_rn(v);
    *ph = h;
    *pl = __float2bfloat16_rn(v - __bfloat162float(h));
}

__global__ void convert_B1(const float* __restrict__ W1a) {
    int idx = blockIdx.x * blockDim.x + threadIdx.x;
    if (idx >= 2 * F2 * FDIM) return;
    int half = idx >= F2 * FDIM;
    int l = idx - half * (F2 * FDIM);
    int n = l >> 7, k = l & 127;
    if (!half)
        split1(&g_Bpre_hi[l], &g_Bpre_lo[l], W1a[(size_t)k * F2 + n]);
    else
        split1(&g_Bedge_hi[l], &g_Bedge_lo[l], W1a[(size_t)(FDIM + k) * F2 + n]);
}

__global__ void __launch_bounds__(512) compute_Wmid(
    const float* __restrict__ W1b, const float* __restrict__ W2a)
{
    __shared__ float sRow[F2];
    int k = blockIdx.x;
    int j = threadIdx.x;
    if (j < F2) sRow[j] = W1b[(size_t)k * F2 + j];
    __syncthreads();
    float acc = 0.f;
    #pragma unroll 4
    for (int m = 0; m < F2; m++)
        acc = fmaf(sRow[m], W2a[(size_t)(128 + m) * F4 + j], acc);
    g_Wmid[(size_t)k * F4 + j] = acc;
}

__global__ void __launch_bounds__(512) compute_vecs(
    const float* __restrict__ b1b, const float* __restrict__ u,
    const float* __restrict__ W2a, const float* __restrict__ b2a)
{
    int j = threadIdx.x;
    float bv = 0.f;
    for (int m = 0; m < F2; m++)
        bv = fmaf(b1b[m], W2a[(size_t)(128 + m) * F4 + j], bv);
    g_bvec[j] = bv;
    float cv = b2a[j];
    for (int k = 0; k < FDIM; k++)
        cv = fmaf(u[k], W2a[(size_t)(384 + k) * F4 + j], cv);
    g_c2[j] = cv;
}

__global__ void convert_Bn1(const float* __restrict__ W2a) {
    int idx = blockIdx.x * blockDim.x + threadIdx.x;
    if (idx >= F4 * 384) return;
    int n = idx / 384, k = idx % 384;
    float v = (k < FDIM) ? W2a[(size_t)k * F4 + n] : g_Wmid[(size_t)(k - FDIM) * F4 + n];
    split1(&g_Bn1_hi[idx], &g_Bn1_lo[idx], v);
}
__global__ void convert_Bn2(const float* __restrict__ W2b) {
    int idx = blockIdx.x * blockDim.x + threadIdx.x;
    if (idx >= FDIM * F4) return;
    int n = idx >> 9, k = idx & 511;
    split1(&g_Bn2_hi[idx], &g_Bn2_lo[idx], W2b[(size_t)k * FDIM + n]);
}

// ---------------------------------------------------------------------------
// GEMM pre: x_s[S,128] @ Bpre^T -> g_P (+ b1a).  N=256, K=128, 2 slabs/iter.
// ---------------------------------------------------------------------------
__global__ void __launch_bounds__(256, 2) gemm_pre(
    const float* __restrict__ x_s, const float* __restrict__ b1a)
{
    int m0 = blockIdx.x * TBM;
    MAKE_LANE(4);
    unsigned base = smem_u32(dsm);
    float acc[16][4] = {};

    for (int kt = 0; kt < FDIM; kt += 32) {
        #pragma unroll
        for (int s = 0; s < 2; s++) {
            int k0 = kt + 16 * s;
            __nv_bfloat16* pAh = dsm + s * AEL;
            __nv_bfloat16* pAl = dsm + 2 * AEL + s * AEL;
            #pragma unroll
            for (int it = 0; it < 2; it++) {
                int p = threadIdx.x + it * 256;
                int row = p >> 3, cp = p & 7;
                int gm = m0 + row;
                float2 v = make_float2(0.f, 0.f);
                if (gm < S_N)
                    v = *reinterpret_cast<const float2*>(
                            x_s + (size_t)gm * FDIM + k0 + 2 * cp);
                split_store(&pAh[row * PA + 2 * cp], &pAl[row * PA + 2 * cp], v);
            }
            __nv_bfloat16* pBh = dsm + 4 * AEL + s * BEL4;
            __nv_bfloat16* pBl = dsm + 4 * AEL + 2 * BEL4 + s * BEL4;
            LOAD_B_SLAB(pBh, pBl, g_Bpre_hi, g_Bpre_lo, FDIM, F2, k0);
        }
        __syncthreads();
        #pragma unroll
        for (int s = 0; s < 2; s++)
            mma_chunk_t<4>(base + OFF_AH(s) + aOff, base + OFF_AL(s) + aOff,
                           base + OFF_BH(s, BEL4) + bOff, base + OFF_BL(s, BEL4) + bOff,
                           acc);
        __syncthreads();
    }

    #pragma unroll
    for (int mi = 0; mi < 2; mi++)
        #pragma unroll
        for (int h = 0; h < 2; h++) {
            int gm = m0 + wm0 + mi * 16 + (lane >> 2) + h * 8;
            if (gm >= S_N) continue;
            #pragma unroll
            for (int ni = 0; ni < 8; ni++) {
                int col = wn0 + ni * 8 + 2 * (lane & 3);
                float2 bb = *reinterpret_cast<const float2*>(b1a + col);
                float2 o;
                o.x = acc[mi * 8 + ni][h * 2 + 0] + bb.x;
                o.y = acc[mi * 8 + ni][h * 2 + 1] + bb.y;
                *reinterpret_cast<float2*>(&g_P[(size_t)gm * F2 + col]) = o;
            }
        }
}

// ---------------------------------------------------------------------------
// GEMM edge (R11 shape, measured 779us): edge_attr[E,128] @ Bedge^T;
// 2-stage double-buffered mainloop; epi leaky(D+P[src]) red.v2 -> aggH.
// TBM=128, 512 threads.
// ---------------------------------------------------------------------------
__global__ void __launch_bounds__(512) gemm_edge(
    const float* __restrict__ edge_attr, const int* __restrict__ eidx)
{
    __shared__ int sSrc[TBME], sTgt[TBME];
    int m0 = blockIdx.x * TBME;

    if (threadIdx.x < TBME) {
        int m = m0 + threadIdx.x;
        int sv = 0, tv = 0;
        if (m < E_N) {
            sv = eidx[m];
            tv = eidx[E_N + m];
            atomicAdd(&g_cnt[tv], 1);
        }
        sSrc[threadIdx.x] = sv;
        sTgt[threadIdx.x] = tv;
    }

    int lane = threadIdx.x & 31;
    int warp = threadIdx.x >> 5;
    int wm0 = (warp >> 2) * 32;
    int wn0 = (warp & 3) * 64;
    unsigned base = smem_u32(dsm);
    unsigned aOff = ((wm0 + ((lane >> 3) & 1) * 8 + (lane & 7)) * PA + (lane >> 4) * 8) * 2;
    unsigned bOff = ((wn0 + (lane >> 4) * 8 + (lane & 7)) * PA + ((lane >> 3) & 1) * 8) * 2;

    float acc[16][4] = {};

    // stage layout (elems): Ah=0, Al=EAE, Bh=2EAE, Bl=2EAE+EBE
    auto load_chunk = [&](int kt, int st) {
        __nv_bfloat16* pAh = dsm + st * ESTAGE;
        __nv_bfloat16* pAl = pAh + EAE;
        __nv_bfloat16* pBh = pAl + EAE;
        __nv_bfloat16* pBl = pBh + EBE;
        #pragma unroll
        for (int it = 0; it < 2; it++) {
            int p = threadIdx.x + it * 512;
            int row = p >> 3, cp = p & 7;
            int gm = m0 + row;
            float2 v = make_float2(0.f, 0.f);
            if (gm < E_N)
                v = *reinterpret_cast<const float2*>(
                        edge_attr + (size_t)gm * FDIM + kt + 2 * cp);
            split_store(&pAh[row * PA + 2 * cp], &pAl[row * PA + 2 * cp], v);
        }
        {
            int p = threadIdx.x;           // 512 == F2*2 chunks
            int n = p >> 1, j = p & 1;
            *reinterpret_cast<uint4*>(&pBh[n * PA + 8 * j]) =
                *reinterpret_cast<const uint4*>(&g_Bedge_hi[(size_t)n * FDIM + kt + 8 * j]);
            *reinterpret_cast<uint4*>(&pBl[n * PA + 8 * j]) =
                *reinterpret_cast<const uint4*>(&g_Bedge_lo[(size_t)n * FDIM + kt + 8 * j]);
        }
    };

    load_chunk(0, 0);
    __syncthreads();

    const int NCH = FDIM / 16;   // 8
    for (int c = 0; c < NCH; c++) {
        int cur = c & 1;
        if (c + 1 < NCH) load_chunk((c + 1) * 16, cur ^ 1);
        unsigned sb = base + cur * (ESTAGE * 2);
        unsigned aH = sb + aOff;
        unsigned aL = sb + EAE * 2 + aOff;
        unsigned bHa = sb + 2 * EAE * 2 + bOff;
        unsigned bLa = sb + (2 * EAE + EBE) * 2 + bOff;
        mma_chunk_t<4>(aH, aL, bHa, bLa, acc);
        __syncthreads();
    }

    #pragma unroll
    for (int mi = 0; mi < 2; mi++)
        #pragma unroll
        for (int h = 0; h < 2; h++) {
            int r = wm0 + mi * 16 + (lane >> 2) + h * 8;
            int gm = m0 + r;
            if (gm >= E_N) continue;
            int s = sSrc[r], t = sTgt[r];
            #pragma unroll
            for (int ni = 0; ni < 8; ni++) {
                int col = wn0 + ni * 8 + 2 * (lane & 3);
                float2 pv = *reinterpret_cast<const float2*>(&g_P[(size_t)s * F2 + col]);
                float v0 = acc[mi * 8 + ni][h * 2 + 0] + pv.x;
                float v1 = acc[mi * 8 + ni][h * 2 + 1] + pv.y;
                v0 = v0 >= 0.f ? v0 : SLOPE * v0;
                v1 = v1 >= 0.f ? v1 : SLOPE * v1;
                red_add_v2(&g_aggH[(size_t)t * F2 + col], v0, v1);
            }
        }
}

// ---------------------------------------------------------------------------
// GEMM node1: [x_t | aggH][T,384] @ Bn1^T; epi leaky(+c2+cnt*bvec) -> g_h3
// ---------------------------------------------------------------------------
__global__ void __launch_bounds__(256, 2) gemm_node1(const float* __restrict__ x_t)
{
    int m0 = blockIdx.y * TBM;
    int n0 = blockIdx.x * F2;
    MAKE_LANE(4);
    unsigned base = smem_u32(dsm);
    float acc[16][4] = {};

    for (int kt = 0; kt < 384; kt += 32) {
        #pragma unroll
        for (int s = 0; s < 2; s++) {
            int k0 = kt + 16 * s;
            __nv_bfloat16* pAh = dsm + s * AEL;
            __nv_bfloat16* pAl = dsm + 2 * AEL + s * AEL;
            #pragma unroll
            for (int it = 0; it < 2; it++) {
                int p = threadIdx.x + it * 256;
                int row = p >> 3, cp = p & 7;
                int gm = m0 + row;
                int gk = k0 + 2 * cp;
                float2 v = make_float2(0.f, 0.f);
                if (gm < T_N) {
                    if (gk < FDIM)
                        v = *reinterpret_cast<const float2*>(x_t + (size_t)gm * FDIM + gk);
                    else
                        v = *reinterpret_cast<const float2*>(
                                &g_aggH[(size_t)gm * F2 + gk - FDIM]);
                }
                split_store(&pAh[row * PA + 2 * cp], &pAl[row * PA + 2 * cp], v);
            }
            const __nv_bfloat16* Bh = g_Bn1_hi + (size_t)n0 * 384;
            const __nv_bfloat16* Bl = g_Bn1_lo + (size_t)n0 * 384;
            __nv_bfloat16* pBh = dsm + 4 * AEL + s * BEL4;
            __nv_bfloat16* pBl = dsm + 4 * AEL + 2 * BEL4 + s * BEL4;
            LOAD_B_SLAB(pBh, pBl, Bh, Bl, 384, F2, k0);
        }
        __syncthreads();
        #pragma unroll
        for (int s = 0; s < 2; s++)
            mma_chunk_t<4>(base + OFF_AH(s) + aOff, base + OFF_AL(s) + aOff,
                           base + OFF_BH(s, BEL4) + bOff, base + OFF_BL(s, BEL4) + bOff,
                           acc);
        __syncthreads();
    }

    #pragma unroll
    for (int mi = 0; mi < 2; mi++)
        #pragma unroll
        for (int h = 0; h < 2; h++) {
            int gm = m0 + wm0 + mi * 16 + (lane >> 2) + h * 8;
            if (gm >= T_N) continue;
            float c = (float)g_cnt[gm];
            #pragma unroll
            for (int ni = 0; ni < 8; ni++) {
                int col = n0 + wn0 + ni * 8 + 2 * (lane & 3);
                float2 c2v = *reinterpret_cast<const float2*>(&g_c2[col]);
                float2 bvv = *reinterpret_cast<const float2*>(&g_bvec[col]);
                float v0 = acc[mi * 8 + ni][h * 2 + 0] + c2v.x + c * bvv.x;
                float v1 = acc[mi * 8 + ni][h * 2 + 1] + c2v.y + c * bvv.y;
                v0 = v0 >= 0.f ? v0 : SLOPE * v0;
                v1 = v1 >= 0.f ? v1 : SLOPE * v1;
                float2 o; o.x = v0; o.y = v1;
                *reinterpret_cast<float2*>(&g_h3[(size_t)gm * F4 + col]) = o;
            }
        }
}

// ---------------------------------------------------------------------------
// GEMM node2: g_h3[T,512] @ Bn2^T (+b2b) -> out.  N=128 (NT=2), K=512.
// ---------------------------------------------------------------------------
__global__ void __launch_bounds__(256, 2) gemm_node2(
    const float* __restrict__ b2b, float* __restrict__ out)
{
    int m0 = blockIdx.x * TBM;
    MAKE_LANE(2);
    unsigned base = smem_u32(dsm);
    float acc[8][4] = {};

    for (int kt = 0; kt < F4; kt += 32) {
        #pragma unroll
        for (int s = 0; s < 2; s++) {
            int k0 = kt + 16 * s;
            __nv_bfloat16* pAh = dsm + s * AEL;
            __nv_bfloat16* pAl = dsm + 2 * AEL + s * AEL;
            #pragma unroll
            for (int it = 0; it < 2; it++) {
                int p = threadIdx.x + it * 256;
                int row = p >> 3, cp = p & 7;
                int gm = m0 + row;
                float2 v = make_float2(0.f, 0.f);
                if (gm < T_N)
                    v = *reinterpret_cast<const float2*>(
                            &g_h3[(size_t)gm * F4 + k0 + 2 * cp]);
                split_store(&pAh[row * PA + 2 * cp], &pAl[row * PA + 2 * cp], v);
            }
            __nv_bfloat16* pBh = dsm + 4 * AEL + s * BEL2;
            __nv_bfloat16* pBl = dsm + 4 * AEL + 2 * BEL2 + s * BEL2;
            LOAD_B_SLAB(pBh, pBl, g_Bn2_hi, g_Bn2_lo, F4, FDIM, k0);
        }
        __syncthreads();
        #pragma unroll
        for (int s = 0; s < 2; s++)
            mma_chunk_t<2>(base + OFF_AH(s) + aOff, base + OFF_AL(s) + aOff,
                           base + OFF_BH(s, BEL2) + bOff, base + OFF_BL(s, BEL2) + bOff,
                           acc);
        __syncthreads();
    }

    #pragma unroll
    for (int mi = 0; mi < 2; mi++)
        #pragma unroll
        for (int h = 0; h < 2; h++) {
            int gm = m0 + wm0 + mi * 16 + (lane >> 2) + h * 8;
            if (gm >= T_N) continue;
            #pragma unroll
            for (int ni = 0; ni < 4; ni++) {
                int col = wn0 + ni * 8 + 2 * (lane & 3);
                float2 bb = *reinterpret_cast<const float2*>(b2b + col);
                float2 o;
                o.x = acc[mi * 4 + ni][h * 2 + 0] + bb.x;
                o.y = acc[mi * 4 + ni][h * 2 + 1] + bb.y;
                *reinterpret_cast<float2*>(&out[(size_t)gm * FDIM + col]) = o;
            }
        }
}

// ---------------------------------------------------------------------------
// BatchNorm
// ---------------------------------------------------------------------------
__global__ void bn_stats(const float* __restrict__ y) {
    int c = threadIdx.x & (FDIM - 1);
    int half = threadIdx.x >> 7;
    double s = 0.0, sq = 0.0;
    for (int m = blockIdx.x * 2 + half; m < T_N; m += gridDim.x * 2) {
        float v = y[(size_t)m * FDIM + c];
        s += v;
        sq += (double)v * (double)v;
    }
    atomicAdd(&g_sum[c], s);
    atomicAdd(&g_sumsq[c], sq);
}

__global__ void bn_norm(float* __restrict__ y,
                        const float* __restrict__ gamma,
                        const float* __restrict__ beta) {
    size_t idx = (size_t)blockIdx.x * blockDim.x + threadIdx.x;
    if (idx >= (size_t)T_N * FDIM) return;
    int c = (int)(idx & (FDIM - 1));
    double mean = g_sum[c] / (double)T_N;
    double var = g_sumsq[c] / (double)T_N - mean * mean;
    float scale = rsqrtf((float)var + BN_EPS) * gamma[c];
    y[idx] = (float)((double)y[idx] - mean) * scale + beta[c];
}

extern "C" void kernel_launch(void* const* d_in, const int* in_sizes, int n_in,
                              void* d_out, int out_size) {
    const float* x_s       = (const float*)d_in[0];
    const float* x_t       = (const float*)d_in[1];
    const float* edge_attr = (const float*)d_in[2];
    const float* u         = (const float*)d_in[3];
    const int*   eidx      = (const int*)d_in[4];
    const float* W1a       = (const float*)d_in[5];
    const float* b1a       = (const float*)d_in[6];
    const float* W1b       = (const float*)d_in[7];
    const float* b1b       = (const float*)d_in[8];
    const float* W2a       = (const float*)d_in[9];
    const float* b2a       = (const float*)d_in[10];
    const float* W2b       = (const float*)d_in[11];
    const float* b2b       = (const float*)d_in[12];
    const float* gamma     = (const float*)d_in[13];
    const float* beta      = (const float*)d_in[14];
    float* out = (float*)d_out;

    static int smem_set = 0;
    if (!smem_set) {
        cudaFuncSetAttribute(gemm_pre,   cudaFuncAttributeMaxDynamicSharedMemorySize, SMEM4);
        cudaFuncSetAttribute(gemm_edge,  cudaFuncAttributeMaxDynamicSharedMemorySize, EDYN);
        cudaFuncSetAttribute(gemm_node1, cudaFuncAttributeMaxDynamicSharedMemorySize, SMEM4);
        cudaFuncSetAttribute(gemm_node2, cudaFuncAttributeMaxDynamicSharedMemorySize, SMEM2);
        smem_set = 1;
    }

    // Launch order chosen so the ncu capture slot (4th launch) is gemm_edge.
    convert_B1<<<(2 * F2 * FDIM + 255) / 256, 256>>>(W1a);           // 1
    zero_kernel<<<1024, 256>>>();                                    // 2

    int mblk = (S_N + TBM - 1) / TBM;               // 782
    gemm_pre<<<mblk, 256, SMEM4>>>(x_s, b1a);                        // 3

    int eblk = (E_N + TBME - 1) / TBME;             // 4688
    gemm_edge<<<eblk, 512, EDYN>>>(edge_attr, eidx);                 // 4

    compute_Wmid<<<F2, 512>>>(W1b, W2a);                             // 5
    compute_vecs<<<1, 512>>>(b1b, u, W2a, b2a);                      // 6
    convert_Bn1<<<(F4 * 384 + 255) / 256, 256>>>(W2a);               // 7
    convert_Bn2<<<(FDIM * F4 + 255) / 256, 256>>>(W2b);              // 8

    dim3 gN1(2, mblk);
    gemm_node1<<<gN1, 256, SMEM4>>>(x_t);                            // 9
    gemm_node2<<<mblk, 256, SMEM2>>>(b2b, out);                      // 10

    bn_stats<<<512, 256>>>(out);                                     // 11
    bn_norm<<<(T_N * FDIM + 255) / 256, 256>>>(out, gamma, beta);    // 12
}